// round 11
// baseline (speedup 1.0000x reference)
#include <cuda_runtime.h>
#include <math.h>

#define NB_ 16
#define NC 64
#define NH 130
#define NKX 66
#define NM 12
#define NE 15
#define NR 4
#define HW (NH*NH)          /* 16900 */
#define BC (NB_*NC)         /* 1024 */

/* ---------------- scratch (device globals, no runtime allocation) -------- */
__device__ float  g_hA[BC*HW];
__device__ float  g_hB[BC*HW];
__device__ float2 g_Modes[BC*24*NM];
__device__ float2 g_OutModes[BC*24*NM];
__device__ float2 g_Ty[BC*NH*NM];
__device__ float  g_sab[BC];
__device__ float  g_gate[NB_*NE];
__device__ float2 g_M1[NE*NC*NC];
__device__ float2 g_M2[NE*NC*NC];
__device__ float2 g_d1[NB_*NC*NC];
__device__ float2 g_d2[NB_*NC*NC];
__device__ float2 g_tw[NH];

__device__ __forceinline__ float gelu_exact(float v){
    return 0.5f*v*(1.f+erff(v*0.70710678118654752f));
}

/* twiddle table: tw[k] = (cos, sin)(2*pi*k/130) */
__global__ void ktw(){
    int k = threadIdx.x;
    if(k < NH){
        double th = 6.283185307179586476925286766559 * (double)k / 130.0;
        g_tw[k] = make_float2((float)cos(th), (float)sin(th));
    }
}

/* lift: h0[b,c,y,x] = concat(x,grid)@fc0_w + fc0_b ; zero pad region */
__global__ void k0(const float* __restrict__ xin, const float* __restrict__ grd,
                   const float* __restrict__ w, const float* __restrict__ bias){
    int y = blockIdx.x, b = blockIdx.y, tid = threadIdx.x;
    __shared__ float in[128*12];
    __shared__ float ws[12*NC];
    __shared__ float bs[NC];
    for(int i=tid;i<12*NC;i+=256) ws[i]=w[i];
    if(tid<NC) bs[tid]=bias[tid];
    if(y<128){
        for(int i=tid;i<128*10;i+=256){ int xx=i/10,t=i%10; in[xx*12+t]=xin[(((size_t)b*128+y)*128+xx)*10+t]; }
        for(int i=tid;i<128*2 ;i+=256){ int xx=i/2 ,t=i%2 ; in[xx*12+10+t]=grd[(((size_t)b*128+y)*128+xx)*2+t]; }
    }
    __syncthreads();
    for(int idx=tid; idx<NC*NH; idx+=256){
        int c=idx/NH, xx=idx%NH;
        float v=0.f;
        if(y<128 && xx<128){
            v=bs[c];
            #pragma unroll
            for(int t=0;t<12;t++) v += in[xx*12+t]*ws[t*NC+c];
        }
        g_hA[(((size_t)b*NC+c)*NH+y)*NH+xx]=v;
    }
}

/* ===================== fused mixed-radix 2D forward FFT ====================
 * 130 = 13*10.  Low-smem version + register twiddle recurrence in B/D. */
__global__ void __launch_bounds__(1024,2) kfft(int curA){
    extern __shared__ unsigned char s_raw[];
    float*  hs  = (float*)s_raw;            /* 130*132 floats; reused as Z/GC */
    float2* GA  = (float2*)(hs + 17160);    /* 65*78 = 5070 float2           */
    float2* tws = GA + 5070;                /* 130 */
    float2* w10 = tws + 130;                /* 100 */
    __shared__ float swred[32];
    int bc = blockIdx.x, tid = threadIdx.x;
    const float* hin = curA ? g_hA : g_hB;
    const float* hp = hin + (size_t)bc*HW;
    for(int i=tid;i<HW;i+=1024){ int y=i/130, x=i-y*130; hs[y*132+x]=hp[i]; }
    for(int i=tid;i<130;i+=1024) tws[i]=g_tw[i];
    for(int i=tid;i<100;i+=1024){ int r=i/10,p=i-r*10; w10[i]=g_tw[13*((r*p)%10)]; }
    __syncthreads();

    float2* zb = (float2*)hs;   /* Z[y][kx] : row y overlays h row y exactly */

    /* stages A+B in two y-halves (GA holds 65 rows) */
    for(int half=0; half<2; half++){
        int ybase = half*65;
        /* stage A: real radix-10 along x; store r=0..5 (Hermitian) */
        for(int it=tid; it<845; it+=1024){
            int yl = it/13, q = it-yl*13;
            int y = ybase + yl;
            float hv[10];
            #pragma unroll
            for(int p=0;p<10;p++) hv[p]=hs[y*132 + 13*p + q];
            float2* ga = GA + yl*78 + q*6;
            #pragma unroll
            for(int r=0;r<6;r++){
                float ar=0.f, ai=0.f;
                #pragma unroll
                for(int p=0;p<10;p++){
                    float2 w = w10[r*10+p];
                    ar += hv[p]*w.x;
                    ai -= hv[p]*w.y;
                }
                ga[r]=make_float2(ar,ai);
            }
        }
        __syncthreads();
        /* stage B: finish x transform; register twiddle recurrence */
        for(int it=tid; it<4290; it+=1024){
            int yl = it/66, kx = it-yl*66;
            int y = ybase + yl;
            int r = kx - (kx/10)*10;
            float sgn = 1.f;
            if(r>5){ r = 10-r; sgn = -1.f; }
            const float2* ga = GA + yl*78 + r;
            float2 wk = tws[kx];
            float wr=1.f, wi=0.f;
            float ar=0.f, ai=0.f;
            #pragma unroll
            for(int q=0;q<13;q++){
                float2 g = ga[q*6];
                float gy = g.y*sgn;
                ar += g.x*wr + gy*wi;
                ai += gy*wr - g.x*wi;
                float nr = wr*wk.x - wi*wk.y;
                wi = wr*wk.y + wi*wk.x;
                wr = nr;
            }
            zb[y*66+kx]=make_float2(ar,ai);
        }
        __syncthreads();
    }

    /* stage C: radix-10 along y, IN-PLACE in zb. */
    for(int it=tid; it<858; it+=1024){
        int q2 = it/66, kx = it-q2*66;
        float2 zp[10];
        #pragma unroll
        for(int p=0;p<10;p++) zp[p]=zb[(13*p+q2)*66 + kx];
        #pragma unroll
        for(int r=0;r<10;r++){
            float ar=0.f, ai=0.f;
            #pragma unroll
            for(int p=0;p<10;p++){
                float2 w = w10[r*10+p];
                ar += zp[p].x*w.x + zp[p].y*w.y;
                ai += zp[p].y*w.x - zp[p].x*w.y;
            }
            zb[(13*r+q2)*66 + kx]=make_float2(ar,ai);
        }
    }
    __syncthreads();

    /* stage D: finish y transform; kx-pair float4; register twiddle recurrence */
    float lsum=0.f;
    for(int it=tid; it<4290; it+=1024){
        int ky = it/33, kxp = it-ky*33, kx0 = kxp*2;
        int r2 = ky - (ky/10)*10;
        float2 wk = tws[ky];
        float wr=1.f, wi=0.f;
        float a0r=0.f,a0i=0.f,a1r=0.f,a1i=0.f;
        #pragma unroll
        for(int q=0;q<13;q++){
            float4 g = *(const float4*)(zb + (13*r2+q)*66 + kx0);
            a0r += g.x*wr + g.y*wi; a0i += g.y*wr - g.x*wi;
            a1r += g.z*wr + g.w*wi; a1i += g.w*wr - g.z*wi;
            float nr = wr*wk.x - wi*wk.y;
            wi = wr*wk.y + wi*wk.x;
            wr = nr;
        }
        lsum += sqrtf(a0r*a0r+a0i*a0i) + sqrtf(a1r*a1r+a1i*a1i);
        if(kx0<NM && (ky<NM || ky>=NH-NM)){
            int jr = (ky<NM)? ky : ky-106;
            g_Modes[((size_t)bc*24+jr)*NM+kx0  ]=make_float2(a0r,a0i);
            g_Modes[((size_t)bc*24+jr)*NM+kx0+1]=make_float2(a1r,a1i);
        }
    }
    for(int o=16;o>0;o>>=1) lsum += __shfl_down_sync(0xffffffffu, lsum, o);
    if((tid&31)==0) swred[tid>>5]=lsum;
    __syncthreads();
    if(tid<32){
        float s = swred[tid];
        for(int o=16;o>0;o>>=1) s += __shfl_down_sync(0xffffffffu, s, o);
        if(tid==0) g_sab[bc]=s/8580.f;
    }
}

/* gate: softmax(sab @ gw + gb) */
__global__ void kgate(const float* __restrict__ gw, const float* __restrict__ gb){
    int b=blockIdx.x, e=threadIdx.x;
    __shared__ float lg[NE];
    if(e<NE){
        float s=gb[e];
        for(int c=0;c<NC;c++) s += g_sab[b*NC+c]*gw[c*NE+e];
        lg[e]=s;
    }
    __syncthreads();
    if(e==0){
        float mx=-1e30f;
        for(int i=0;i<NE;i++) mx=fmaxf(mx,lg[i]);
        float den=0.f;
        for(int i=0;i<NE;i++){ lg[i]=expf(lg[i]-mx); den+=lg[i]; }
        for(int i=0;i<NE;i++) g_gate[b*NE+i]=lg[i]/den;
    }
}

/* M[e] = A[e] @ B[e]  (complex low-rank products, layer weights) */
__global__ void km(const float* __restrict__ A1,const float* __restrict__ B1,
                   const float* __restrict__ A2,const float* __restrict__ B2){
    int e=blockIdx.x, which=blockIdx.y;
    const float* A  = which? A2:A1;
    const float* Bm = which? B2:B1;
    float2* Mo = which? g_M2:g_M1;
    __shared__ float2 as[NC*NR], bs[NR*NC];
    for(int i=threadIdx.x;i<NC*NR;i+=blockDim.x){
        as[i]=make_float2(A [(e*NC*NR+i)*2], A [(e*NC*NR+i)*2+1]);
        bs[i]=make_float2(Bm[(e*NR*NC+i)*2], Bm[(e*NR*NC+i)*2+1]);
    }
    __syncthreads();
    for(int idx=threadIdx.x; idx<NC*NC; idx+=blockDim.x){
        int i=idx/NC, o=idx%NC;
        float rr=0.f, ri=0.f;
        #pragma unroll
        for(int r=0;r<NR;r++){
            float2 a=as[i*NR+r], b2=bs[r*NC+o];
            rr += a.x*b2.x - a.y*b2.y;
            ri += a.x*b2.y + a.y*b2.x;
        }
        Mo[e*NC*NC+idx]=make_float2(rr,ri);
    }
}

/* d[b] = 0.1 * sum_e g[b,e] M[e] */
__global__ void kd(){
    int b=blockIdx.x, which=blockIdx.y;
    const float2* Mm = which? g_M2 : g_M1;
    float2* dd = which? g_d2 : g_d1;
    __shared__ float gs[NE];
    if(threadIdx.x<NE) gs[threadIdx.x]=g_gate[b*NE+threadIdx.x];
    __syncthreads();
    for(int idx=threadIdx.x; idx<NC*NC; idx+=blockDim.x){
        float rr=0.f, ri=0.f;
        #pragma unroll
        for(int e=0;e<NE;e++){
            float2 m=Mm[e*NC*NC+idx];
            rr += gs[e]*m.x; ri += gs[e]*m.y;
        }
        dd[b*NC*NC+idx]=make_float2(0.1f*rr,0.1f*ri);
    }
}

/* mode mixing: o[b,o,p,q] = sum_i ft[b,i,p,q] * (W[i,o,p,q] + d[b,i,o]) */
__global__ void kmix(const float* __restrict__ W1,const float* __restrict__ W2){
    extern __shared__ unsigned char s_raw[];
    float2* tops = (float2*)s_raw;       /* 64*144 */
    float2* ds   = tops + NC*144;        /* 64*8 */
    int ot=blockIdx.x, half=blockIdx.y, b=blockIdx.z;
    const float2* W    = (const float2*)(half? W2:W1);
    const float2* dmat = half? g_d2 : g_d1;
    int jbase = half*NM;
    for(int i=threadIdx.x;i<NC*144;i+=256){
        int c=i/144, pq=i%144;
        tops[i]=g_Modes[(((size_t)b*NC+c)*24 + jbase + pq/NM)*NM + pq%NM];
    }
    for(int i=threadIdx.x;i<NC*8;i+=256){
        int c=i/8, oo=i%8;
        ds[i]=dmat[((size_t)b*NC+c)*NC + ot*8+oo];
    }
    __syncthreads();
    for(int idx=threadIdx.x; idx<8*144; idx+=256){
        int oo=idx/144, pq=idx%144; int o=ot*8+oo;
        float rr=0.f, ri=0.f;
        #pragma unroll 8
        for(int i=0;i<NC;i++){
            float2 t=tops[i*144+pq];
            float2 d=ds[i*8+oo];
            float2 w=W[((size_t)i*NC+o)*144+pq];
            float wr=w.x+d.x, wi=w.y+d.y;
            rr += t.x*wr - t.y*wi;
            ri += t.x*wi + t.y*wr;
        }
        g_OutModes[(((size_t)b*NC+o)*24 + jbase + pq/NM)*NM + pq%NM]=make_float2(rr,ri);
    }
}

/* inverse fft along y (only 24 nonzero bins): Ty[y,q] */
__global__ void kinv1(){
    __shared__ float2 om[24*NM];
    __shared__ float2 tws[NH];
    int bc=blockIdx.x, tid=threadIdx.x;
    for(int i=tid;i<24*NM;i+=blockDim.x) om[i]=g_OutModes[(size_t)bc*24*NM+i];
    for(int i=tid;i<NH;i+=blockDim.x) tws[i]=g_tw[i];
    __syncthreads();
    for(int idx=tid; idx<NH*NM; idx+=blockDim.x){
        int y=idx/NM, q=idx%NM;
        float rr=0.f, ri=0.f;
        #pragma unroll
        for(int j=0;j<24;j++){
            int ky = (j<NM)? j : j+106;
            int t = (ky*y)%NH;
            float2 w=tws[t];
            float2 o=om[j*NM+q];
            rr += o.x*w.x - o.y*w.y;
            ri += o.x*w.y + o.y*w.x;
        }
        g_Ty[(size_t)bc*NH*NM+idx]=make_float2(rr*(1.f/130.f), ri*(1.f/130.f));
    }
}

/* fused: irfft along x + pointwise conv + bias + (gelu) -> new h
 * mapping: unit u -> oq = u&15 (o-quad), g = u>>4 (x-group).
 * Per 8-lane phase: same g (h4/Ew broadcast), consecutive oq
 * (cwsT/tysT at 4-word lane stride -> conflict-free). */
__global__ void __launch_bounds__(256) kfinal(int curA, const float* __restrict__ cw,
                       const float* __restrict__ cb, int dogelu){
    extern __shared__ unsigned char s_raw[];
    float*  hs   = (float*)s_raw;            /* 64*132, x padded          */
    float*  cwsT = hs + NC*132;              /* [i][o] stride 68 -> 4352  */
    float*  cbs  = cwsT + NC*68;             /* 64                        */
    float2* tysT = (float2*)(cbs + NC);      /* [q][o] 12*64 = 768        */
    float2* Ews  = tysT + 12*64;             /* [x][q] 130*13 = 1690      */
    const float* hin  = curA ? g_hA : g_hB;
    float*       hout = curA ? g_hB : g_hA;
    int y=blockIdx.x, b=blockIdx.y, tid=threadIdx.x;
    for(int i=tid;i<NC*NH;i+=256){ int c=i/NH,x=i-c*NH; hs[c*132+x]=hin[(((size_t)b*NC+c)*NH+y)*NH+x]; }
    for(int i=tid;i<NC*2;i+=256){ int c=i>>1; hs[c*132+130+(i&1)]=0.f; }
    for(int i=tid;i<NC*NC;i+=256){ int o=i>>6, ii=i&63; cwsT[ii*68+o]=cw[i]; }
    if(tid<NC) cbs[tid]=cb[tid];
    for(int i=tid;i<12*NC;i+=256){ int q=i>>6, c=i&63; tysT[q*64+c]=g_Ty[((size_t)(b*NC+c)*NH+y)*NM+q]; }
    for(int i=tid;i<NH*13;i+=256){
        int x=i/13, q=i-13*x;
        float2 v;
        if(q==0)      v=make_float2(0.5f,0.f);
        else if(q<NM) v=g_tw[(q*x)%NH];
        else          v=make_float2(0.f,0.f);
        Ews[x*13+q]=v;
    }
    __syncthreads();
    const float4* h4 = (const float4*)hs;
    for(int u=tid; u<528; u+=256){
        int oq = u & 15, g = u >> 4;
        int o0 = oq*4, x0 = g*4;
        /* pointwise conv: h4 broadcast over phase, cwsT 4-word lane stride */
        float acc[4][4];
        #pragma unroll
        for(int o=0;o<4;o++){
            float c0=cbs[o0+o];
            acc[o][0]=c0; acc[o][1]=c0; acc[o][2]=c0; acc[o][3]=c0;
        }
        #pragma unroll 8
        for(int i=0;i<NC;i++){
            float4 hv = h4[i*33+g];
            float4 c  = *(const float4*)(cwsT + i*68 + o0);
            acc[0][0]+=c.x*hv.x; acc[0][1]+=c.x*hv.y; acc[0][2]+=c.x*hv.z; acc[0][3]+=c.x*hv.w;
            acc[1][0]+=c.y*hv.x; acc[1][1]+=c.y*hv.y; acc[1][2]+=c.y*hv.z; acc[1][3]+=c.y*hv.w;
            acc[2][0]+=c.z*hv.x; acc[2][1]+=c.z*hv.y; acc[2][2]+=c.z*hv.z; acc[2][3]+=c.z*hv.w;
            acc[3][0]+=c.w*hv.x; acc[3][1]+=c.w*hv.y; acc[3][2]+=c.w*hv.z; acc[3][3]+=c.w*hv.w;
        }
        /* spectral irfft along x: Ew broadcast, tysT conflict-free */
        float sac[4][4];
        #pragma unroll
        for(int o=0;o<4;o++){ sac[o][0]=0.f; sac[o][1]=0.f; sac[o][2]=0.f; sac[o][3]=0.f; }
        int xa[4];
        #pragma unroll
        for(int a=0;a<4;a++){ int xx=x0+a; xa[a]=(xx<NH)?xx:0; }
        #pragma unroll
        for(int q=0;q<NM;q++){
            float4 ta = *(const float4*)(tysT + q*64 + o0);      /* o0,o0+1 */
            float4 tb = *(const float4*)(tysT + q*64 + o0 + 2);  /* o0+2,o0+3 */
            #pragma unroll
            for(int a=0;a<4;a++){
                float2 e = Ews[xa[a]*13+q];
                sac[0][a] += ta.x*e.x - ta.y*e.y;
                sac[1][a] += ta.z*e.x - ta.w*e.y;
                sac[2][a] += tb.x*e.x - tb.y*e.y;
                sac[3][a] += tb.z*e.x - tb.w*e.y;
            }
        }
        #pragma unroll
        for(int o=0;o<4;o++){
            float* op = hout + (((size_t)b*NC+o0+o)*NH+y)*NH;
            #pragma unroll
            for(int a=0;a<4;a++){
                int x=x0+a; if(x>=NH) break;
                float v = sac[o][a]*(2.f/130.f) + acc[o][a];
                if(dogelu) v = gelu_exact(v);
                op[x]=v;
            }
        }
    }
}

/* head: crop + fc1 + gelu + fc2 (j-tiled x4 with float4 weight broadcast) */
__global__ void __launch_bounds__(128) kout(const float* __restrict__ f1w,
        const float* __restrict__ f1b, const float* __restrict__ f2w,
        const float* __restrict__ f2b, float* __restrict__ out){
    extern __shared__ unsigned char s_raw[];
    float* hs  = (float*)s_raw;     /* 64*128 */
    float* w1s = hs + 8192;         /* 8192 */
    float* b1s = w1s + 8192;        /* 128 */
    float* w2s = b1s + 128;         /* 128 */
    int y=blockIdx.x, b=blockIdx.y, tid=threadIdx.x;
    for(int i=tid;i<8192;i+=128){ int c=i>>7,x=i&127; hs[i]=g_hA[(((size_t)b*NC+c)*NH+y)*NH+x]; }
    for(int i=tid;i<8192;i+=128) w1s[i]=f1w[i];
    if(tid<128){ b1s[tid]=f1b[tid]; w2s[tid]=f2w[tid]; }
    __syncthreads();
    int x=tid;
    float v[NC];
    #pragma unroll
    for(int i=0;i<NC;i++) v[i]=hs[i*128+x];
    const float4* w14 = (const float4*)w1s;
    float acc=f2b[0];
    for(int j=0;j<128;j+=4){
        float s0=b1s[j], s1=b1s[j+1], s2=b1s[j+2], s3=b1s[j+3];
        #pragma unroll
        for(int i=0;i<NC;i++){
            float4 w = w14[(i*128+j)>>2];
            float vi = v[i];
            s0+=vi*w.x; s1+=vi*w.y; s2+=vi*w.z; s3+=vi*w.w;
        }
        acc += gelu_exact(s0)*w2s[j]   + gelu_exact(s1)*w2s[j+1]
             + gelu_exact(s2)*w2s[j+2] + gelu_exact(s3)*w2s[j+3];
    }
    out[((size_t)(b*128+y))*128+x]=acc;
}

/* ------------------------------- host ------------------------------------ */
extern "C" void kernel_launch(void* const* d_in, const int* in_sizes, int n_in,
                              void* d_out, int out_size){
    const float* x    =(const float*)d_in[0];
    const float* grd  =(const float*)d_in[1];
    const float* fc0w =(const float*)d_in[2];
    const float* fc0b =(const float*)d_in[3];
    const float* W1   =(const float*)d_in[4];
    const float* W2   =(const float*)d_in[5];
    const float* A1   =(const float*)d_in[6];
    const float* B1   =(const float*)d_in[7];
    const float* A2   =(const float*)d_in[8];
    const float* B2   =(const float*)d_in[9];
    const float* gw   =(const float*)d_in[10];
    const float* gb   =(const float*)d_in[11];
    const float* cw   =(const float*)d_in[12];
    const float* cb   =(const float*)d_in[13];
    const float* f1w  =(const float*)d_in[14];
    const float* f1b  =(const float*)d_in[15];
    const float* f2w  =(const float*)d_in[16];
    const float* f2b  =(const float*)d_in[17];
    float* out=(float*)d_out;

    const int SMFFT = 17160*4 + 5070*8 + 130*8 + 100*8;             /* 111040 */
    const int SMMIX = NC*144*8 + NC*8*8;                            /* 77824  */
    const int SMF   = (NC*132 + NC*68 + NC)*4 + (12*64 + 130*13)*8; /* 71120  */
    const int SMO   = (8192+8192+128+128)*4;                        /* 66560  */

    cudaFuncSetAttribute(kfft,   cudaFuncAttributeMaxDynamicSharedMemorySize, SMFFT);
    cudaFuncSetAttribute(kmix,   cudaFuncAttributeMaxDynamicSharedMemorySize, SMMIX);
    cudaFuncSetAttribute(kfinal, cudaFuncAttributeMaxDynamicSharedMemorySize, SMF);
    cudaFuncSetAttribute(kout,   cudaFuncAttributeMaxDynamicSharedMemorySize, SMO);

    ktw<<<1,160>>>();
    k0<<<dim3(NH,NB_),256>>>(x,grd,fc0w,fc0b);

    for(int l=0;l<4;l++){
        int curA = (l%2==0) ? 1 : 0;
        km<<<dim3(NE,2),256>>>(A1+(size_t)l*NE*NC*NR*2, B1+(size_t)l*NE*NR*NC*2,
                               A2+(size_t)l*NE*NC*NR*2, B2+(size_t)l*NE*NR*NC*2);
        kfft<<<BC,1024,SMFFT>>>(curA);
        kgate<<<NB_,32>>>(gw + (size_t)l*NC*NE, gb + (size_t)l*NE);
        kd<<<dim3(NB_,2),256>>>();
        kmix<<<dim3(8,2,NB_),256,SMMIX>>>(W1+(size_t)l*NC*NC*NM*NM*2,
                                          W2+(size_t)l*NC*NC*NM*NM*2);
        kinv1<<<BC,512>>>();
        kfinal<<<dim3(NH,NB_),256,SMF>>>(curA, cw+(size_t)l*NC*NC,
                                         cb+(size_t)l*NC, (l<3)?1:0);
    }
    kout<<<dim3(128,NB_),128,SMO>>>(f1w,f1b,f2w,f2b,out);
}

// round 12
// speedup vs baseline: 1.0921x; 1.0921x over previous
#include <cuda_runtime.h>
#include <math.h>

#define NB_ 16
#define NC 64
#define NH 130
#define NKX 66
#define NM 12
#define NE 15
#define NR 4
#define HW (NH*NH)          /* 16900 */
#define BC (NB_*NC)         /* 1024 */

/* ---------------- scratch (device globals, no runtime allocation) -------- */
__device__ float  g_hA[BC*HW];
__device__ float  g_hB[BC*HW];
__device__ float2 g_Modes[BC*24*NM];
__device__ float2 g_OutModes[BC*24*NM];
__device__ float2 g_Ty[BC*NH*NM];
__device__ float  g_sab[BC];
__device__ float  g_gate[NB_*NE];
__device__ float2 g_M1[NE*NC*NC];
__device__ float2 g_M2[NE*NC*NC];
__device__ float2 g_d1[NB_*NC*NC];
__device__ float2 g_d2[NB_*NC*NC];
__device__ float2 g_tw[NH];

__device__ __forceinline__ float gelu_exact(float v){
    return 0.5f*v*(1.f+erff(v*0.70710678118654752f));
}

/* twiddle table: tw[k] = (cos, sin)(2*pi*k/130) */
__global__ void ktw(){
    int k = threadIdx.x;
    if(k < NH){
        double th = 6.283185307179586476925286766559 * (double)k / 130.0;
        g_tw[k] = make_float2((float)cos(th), (float)sin(th));
    }
}

/* lift: h0[b,c,y,x] = concat(x,grid)@fc0_w + fc0_b ; zero pad region */
__global__ void k0(const float* __restrict__ xin, const float* __restrict__ grd,
                   const float* __restrict__ w, const float* __restrict__ bias){
    int y = blockIdx.x, b = blockIdx.y, tid = threadIdx.x;
    __shared__ float in[128*12];
    __shared__ float ws[12*NC];
    __shared__ float bs[NC];
    for(int i=tid;i<12*NC;i+=256) ws[i]=w[i];
    if(tid<NC) bs[tid]=bias[tid];
    if(y<128){
        for(int i=tid;i<128*10;i+=256){ int xx=i/10,t=i%10; in[xx*12+t]=xin[(((size_t)b*128+y)*128+xx)*10+t]; }
        for(int i=tid;i<128*2 ;i+=256){ int xx=i/2 ,t=i%2 ; in[xx*12+10+t]=grd[(((size_t)b*128+y)*128+xx)*2+t]; }
    }
    __syncthreads();
    for(int idx=tid; idx<NC*NH; idx+=256){
        int c=idx/NH, xx=idx%NH;
        float v=0.f;
        if(y<128 && xx<128){
            v=bs[c];
            #pragma unroll
            for(int t=0;t<12;t++) v += in[xx*12+t]*ws[t*NC+c];
        }
        g_hA[(((size_t)b*NC+c)*NH+y)*NH+xx]=v;
    }
}

/* ===================== fused mixed-radix 2D forward FFT ====================
 * 130 = 13*10.  Low-smem version + register twiddle recurrence in B/D. */
__global__ void __launch_bounds__(1024,2) kfft(int curA){
    extern __shared__ unsigned char s_raw[];
    float*  hs  = (float*)s_raw;            /* 130*132 floats; reused as Z/GC */
    float2* GA  = (float2*)(hs + 17160);    /* 65*78 = 5070 float2           */
    float2* tws = GA + 5070;                /* 130 */
    float2* w10 = tws + 130;                /* 100 */
    __shared__ float swred[32];
    int bc = blockIdx.x, tid = threadIdx.x;
    const float* hin = curA ? g_hA : g_hB;
    const float* hp = hin + (size_t)bc*HW;
    for(int i=tid;i<HW;i+=1024){ int y=i/130, x=i-y*130; hs[y*132+x]=hp[i]; }
    for(int i=tid;i<130;i+=1024) tws[i]=g_tw[i];
    for(int i=tid;i<100;i+=1024){ int r=i/10,p=i-r*10; w10[i]=g_tw[13*((r*p)%10)]; }
    __syncthreads();

    float2* zb = (float2*)hs;   /* Z[y][kx] : row y overlays h row y exactly */

    /* stages A+B in two y-halves (GA holds 65 rows) */
    for(int half=0; half<2; half++){
        int ybase = half*65;
        /* stage A: real radix-10 along x; store r=0..5 (Hermitian) */
        for(int it=tid; it<845; it+=1024){
            int yl = it/13, q = it-yl*13;
            int y = ybase + yl;
            float hv[10];
            #pragma unroll
            for(int p=0;p<10;p++) hv[p]=hs[y*132 + 13*p + q];
            float2* ga = GA + yl*78 + q*6;
            #pragma unroll
            for(int r=0;r<6;r++){
                float ar=0.f, ai=0.f;
                #pragma unroll
                for(int p=0;p<10;p++){
                    float2 w = w10[r*10+p];
                    ar += hv[p]*w.x;
                    ai -= hv[p]*w.y;
                }
                ga[r]=make_float2(ar,ai);
            }
        }
        __syncthreads();
        /* stage B: finish x transform; register twiddle recurrence */
        for(int it=tid; it<4290; it+=1024){
            int yl = it/66, kx = it-yl*66;
            int y = ybase + yl;
            int r = kx - (kx/10)*10;
            float sgn = 1.f;
            if(r>5){ r = 10-r; sgn = -1.f; }
            const float2* ga = GA + yl*78 + r;
            float2 wk = tws[kx];
            float wr=1.f, wi=0.f;
            float ar=0.f, ai=0.f;
            #pragma unroll
            for(int q=0;q<13;q++){
                float2 g = ga[q*6];
                float gy = g.y*sgn;
                ar += g.x*wr + gy*wi;
                ai += gy*wr - g.x*wi;
                float nr = wr*wk.x - wi*wk.y;
                wi = wr*wk.y + wi*wk.x;
                wr = nr;
            }
            zb[y*66+kx]=make_float2(ar,ai);
        }
        __syncthreads();
    }

    /* stage C: radix-10 along y, IN-PLACE in zb. */
    for(int it=tid; it<858; it+=1024){
        int q2 = it/66, kx = it-q2*66;
        float2 zp[10];
        #pragma unroll
        for(int p=0;p<10;p++) zp[p]=zb[(13*p+q2)*66 + kx];
        #pragma unroll
        for(int r=0;r<10;r++){
            float ar=0.f, ai=0.f;
            #pragma unroll
            for(int p=0;p<10;p++){
                float2 w = w10[r*10+p];
                ar += zp[p].x*w.x + zp[p].y*w.y;
                ai += zp[p].y*w.x - zp[p].x*w.y;
            }
            zb[(13*r+q2)*66 + kx]=make_float2(ar,ai);
        }
    }
    __syncthreads();

    /* stage D: finish y transform; kx-pair float4; register twiddle recurrence */
    float lsum=0.f;
    for(int it=tid; it<4290; it+=1024){
        int ky = it/33, kxp = it-ky*33, kx0 = kxp*2;
        int r2 = ky - (ky/10)*10;
        float2 wk = tws[ky];
        float wr=1.f, wi=0.f;
        float a0r=0.f,a0i=0.f,a1r=0.f,a1i=0.f;
        #pragma unroll
        for(int q=0;q<13;q++){
            float4 g = *(const float4*)(zb + (13*r2+q)*66 + kx0);
            a0r += g.x*wr + g.y*wi; a0i += g.y*wr - g.x*wi;
            a1r += g.z*wr + g.w*wi; a1i += g.w*wr - g.z*wi;
            float nr = wr*wk.x - wi*wk.y;
            wi = wr*wk.y + wi*wk.x;
            wr = nr;
        }
        lsum += sqrtf(a0r*a0r+a0i*a0i) + sqrtf(a1r*a1r+a1i*a1i);
        if(kx0<NM && (ky<NM || ky>=NH-NM)){
            int jr = (ky<NM)? ky : ky-106;
            g_Modes[((size_t)bc*24+jr)*NM+kx0  ]=make_float2(a0r,a0i);
            g_Modes[((size_t)bc*24+jr)*NM+kx0+1]=make_float2(a1r,a1i);
        }
    }
    for(int o=16;o>0;o>>=1) lsum += __shfl_down_sync(0xffffffffu, lsum, o);
    if((tid&31)==0) swred[tid>>5]=lsum;
    __syncthreads();
    if(tid<32){
        float s = swred[tid];
        for(int o=16;o>0;o>>=1) s += __shfl_down_sync(0xffffffffu, s, o);
        if(tid==0) g_sab[bc]=s/8580.f;
    }
}

/* gate: softmax(sab @ gw + gb) */
__global__ void kgate(const float* __restrict__ gw, const float* __restrict__ gb){
    int b=blockIdx.x, e=threadIdx.x;
    __shared__ float lg[NE];
    if(e<NE){
        float s=gb[e];
        for(int c=0;c<NC;c++) s += g_sab[b*NC+c]*gw[c*NE+e];
        lg[e]=s;
    }
    __syncthreads();
    if(e==0){
        float mx=-1e30f;
        for(int i=0;i<NE;i++) mx=fmaxf(mx,lg[i]);
        float den=0.f;
        for(int i=0;i<NE;i++){ lg[i]=expf(lg[i]-mx); den+=lg[i]; }
        for(int i=0;i<NE;i++) g_gate[b*NE+i]=lg[i]/den;
    }
}

/* M[e] = A[e] @ B[e]  (complex low-rank products, layer weights) */
__global__ void km(const float* __restrict__ A1,const float* __restrict__ B1,
                   const float* __restrict__ A2,const float* __restrict__ B2){
    int e=blockIdx.x, which=blockIdx.y;
    const float* A  = which? A2:A1;
    const float* Bm = which? B2:B1;
    float2* Mo = which? g_M2:g_M1;
    __shared__ float2 as[NC*NR], bs[NR*NC];
    for(int i=threadIdx.x;i<NC*NR;i+=blockDim.x){
        as[i]=make_float2(A [(e*NC*NR+i)*2], A [(e*NC*NR+i)*2+1]);
        bs[i]=make_float2(Bm[(e*NR*NC+i)*2], Bm[(e*NR*NC+i)*2+1]);
    }
    __syncthreads();
    for(int idx=threadIdx.x; idx<NC*NC; idx+=blockDim.x){
        int i=idx/NC, o=idx%NC;
        float rr=0.f, ri=0.f;
        #pragma unroll
        for(int r=0;r<NR;r++){
            float2 a=as[i*NR+r], b2=bs[r*NC+o];
            rr += a.x*b2.x - a.y*b2.y;
            ri += a.x*b2.y + a.y*b2.x;
        }
        Mo[e*NC*NC+idx]=make_float2(rr,ri);
    }
}

/* d[b] = 0.1 * sum_e g[b,e] M[e] */
__global__ void kd(){
    int b=blockIdx.x, which=blockIdx.y;
    const float2* Mm = which? g_M2 : g_M1;
    float2* dd = which? g_d2 : g_d1;
    __shared__ float gs[NE];
    if(threadIdx.x<NE) gs[threadIdx.x]=g_gate[b*NE+threadIdx.x];
    __syncthreads();
    for(int idx=threadIdx.x; idx<NC*NC; idx+=blockDim.x){
        float rr=0.f, ri=0.f;
        #pragma unroll
        for(int e=0;e<NE;e++){
            float2 m=Mm[e*NC*NC+idx];
            rr += gs[e]*m.x; ri += gs[e]*m.y;
        }
        dd[b*NC*NC+idx]=make_float2(0.1f*rr,0.1f*ri);
    }
}

/* mode mixing: o[b,o,p,q] = sum_i ft[b,i,p,q] * (W[i,o,p,q] + d[b,i,o]) */
__global__ void kmix(const float* __restrict__ W1,const float* __restrict__ W2){
    extern __shared__ unsigned char s_raw[];
    float2* tops = (float2*)s_raw;       /* 64*144 */
    float2* ds   = tops + NC*144;        /* 64*8 */
    int ot=blockIdx.x, half=blockIdx.y, b=blockIdx.z;
    const float2* W    = (const float2*)(half? W2:W1);
    const float2* dmat = half? g_d2 : g_d1;
    int jbase = half*NM;
    for(int i=threadIdx.x;i<NC*144;i+=256){
        int c=i/144, pq=i%144;
        tops[i]=g_Modes[(((size_t)b*NC+c)*24 + jbase + pq/NM)*NM + pq%NM];
    }
    for(int i=threadIdx.x;i<NC*8;i+=256){
        int c=i/8, oo=i%8;
        ds[i]=dmat[((size_t)b*NC+c)*NC + ot*8+oo];
    }
    __syncthreads();
    for(int idx=threadIdx.x; idx<8*144; idx+=256){
        int oo=idx/144, pq=idx%144; int o=ot*8+oo;
        float rr=0.f, ri=0.f;
        #pragma unroll 8
        for(int i=0;i<NC;i++){
            float2 t=tops[i*144+pq];
            float2 d=ds[i*8+oo];
            float2 w=W[((size_t)i*NC+o)*144+pq];
            float wr=w.x+d.x, wi=w.y+d.y;
            rr += t.x*wr - t.y*wi;
            ri += t.x*wi + t.y*wr;
        }
        g_OutModes[(((size_t)b*NC+o)*24 + jbase + pq/NM)*NM + pq%NM]=make_float2(rr,ri);
    }
}

/* inverse fft along y (only 24 nonzero bins): Ty[y,q] */
__global__ void kinv1(){
    __shared__ float2 om[24*NM];
    __shared__ float2 tws[NH];
    int bc=blockIdx.x, tid=threadIdx.x;
    for(int i=tid;i<24*NM;i+=blockDim.x) om[i]=g_OutModes[(size_t)bc*24*NM+i];
    for(int i=tid;i<NH;i+=blockDim.x) tws[i]=g_tw[i];
    __syncthreads();
    for(int idx=tid; idx<NH*NM; idx+=blockDim.x){
        int y=idx/NM, q=idx%NM;
        float rr=0.f, ri=0.f;
        #pragma unroll
        for(int j=0;j<24;j++){
            int ky = (j<NM)? j : j+106;
            int t = (ky*y)%NH;
            float2 w=tws[t];
            float2 o=om[j*NM+q];
            rr += o.x*w.x - o.y*w.y;
            ri += o.x*w.y + o.y*w.x;
        }
        g_Ty[(size_t)bc*NH*NM+idx]=make_float2(rr*(1.f/130.f), ri*(1.f/130.f));
    }
}

/* fused: irfft along x + pointwise conv + bias + (gelu) -> new h
 * o-tiled: each unit = 4 o x 4 x outputs, h4 loads shared across the 4 o's. */
__global__ void __launch_bounds__(256) kfinal(int curA, const float* __restrict__ cw,
                       const float* __restrict__ cb, int dogelu){
    extern __shared__ unsigned char s_raw[];
    float*  hs   = (float*)s_raw;           /* 64*132 floats, x padded */
    float*  cws  = hs + NC*132;             /* 4096 */
    float*  cbs  = cws + NC*NC;             /* 64 */
    float2* tys  = (float2*)(cbs + NC);     /* 64*12 */
    float2* twsl = tys + NC*NM;             /* 130 */
    const float* hin  = curA ? g_hA : g_hB;
    float*       hout = curA ? g_hB : g_hA;
    int y=blockIdx.x, b=blockIdx.y, tid=threadIdx.x;
    for(int i=tid;i<NC*NH;i+=256){ int c=i/NH,x=i-c*NH; hs[c*132+x]=hin[(((size_t)b*NC+c)*NH+y)*NH+x]; }
    for(int i=tid;i<NC*2;i+=256){ int c=i>>1; hs[c*132+130+(i&1)]=0.f; }
    for(int i=tid;i<NC*NC;i+=256) cws[i]=cw[i];
    if(tid<NC) cbs[tid]=cb[tid];
    for(int i=tid;i<NC*NM;i+=256){ int c=i/NM,q=i-c*NM; tys[i]=g_Ty[((size_t)(b*NC+c)*NH+y)*NM+q]; }
    for(int i=tid;i<NH;i+=256) twsl[i]=g_tw[i];
    __syncthreads();
    const float4* h4 = (const float4*)hs;
    for(int u=tid; u<528; u+=256){       /* 16 o-quads x 33 x-groups */
        int g = u % 33, oq = u / 33;
        int o0 = oq*4, x0 = g*4;
        /* pointwise conv: 4 o x 4 x, h4 loads reused across o */
        float acc[4][4];
        #pragma unroll
        for(int o=0;o<4;o++){
            float c0=cbs[o0+o];
            acc[o][0]=c0; acc[o][1]=c0; acc[o][2]=c0; acc[o][3]=c0;
        }
        #pragma unroll 4
        for(int i4=0;i4<16;i4++){
            float4 h0=h4[(i4*4+0)*33+g];
            float4 h1=h4[(i4*4+1)*33+g];
            float4 h2=h4[(i4*4+2)*33+g];
            float4 h3=h4[(i4*4+3)*33+g];
            #pragma unroll
            for(int o=0;o<4;o++){
                float4 c = *(const float4*)(cws + (o0+o)*NC + i4*4);
                acc[o][0] += c.x*h0.x + c.y*h1.x + c.z*h2.x + c.w*h3.x;
                acc[o][1] += c.x*h0.y + c.y*h1.y + c.z*h2.y + c.w*h3.y;
                acc[o][2] += c.x*h0.z + c.y*h1.z + c.z*h2.z + c.w*h3.z;
                acc[o][3] += c.x*h0.w + c.y*h1.w + c.z*h2.w + c.w*h3.w;
            }
        }
        /* spectral irfft along x + store, per o */
        #pragma unroll
        for(int o=0;o<4;o++){
            const float2* ty = tys + (o0+o)*NM;
            float2 t0=ty[0];
            float sac[4];
            int id[4], xa[4];
            #pragma unroll
            for(int a=0;a<4;a++){ sac[a]=t0.x; id[a]=0; xa[a]=(x0+a<NH)?(x0+a):0; }
            #pragma unroll
            for(int q=1;q<NM;q++){
                float2 t=ty[q];
                #pragma unroll
                for(int a=0;a<4;a++){
                    id[a]+=xa[a]; if(id[a]>=NH) id[a]-=NH;
                    float2 w=twsl[id[a]];
                    sac[a] += 2.f*(t.x*w.x - t.y*w.y);
                }
            }
            float* op = hout + (((size_t)b*NC+o0+o)*NH+y)*NH;
            #pragma unroll
            for(int a=0;a<4;a++){
                int x=x0+a; if(x>=NH) break;
                float v = sac[a]*(1.f/130.f) + acc[o][a];
                if(dogelu) v = gelu_exact(v);
                op[x]=v;
            }
        }
    }
}

/* head: crop + fc1 + gelu + fc2 (j-tiled x4 with float4 weight broadcast) */
__global__ void __launch_bounds__(128) kout(const float* __restrict__ f1w,
        const float* __restrict__ f1b, const float* __restrict__ f2w,
        const float* __restrict__ f2b, float* __restrict__ out){
    extern __shared__ unsigned char s_raw[];
    float* hs  = (float*)s_raw;     /* 64*128 */
    float* w1s = hs + 8192;         /* 8192 */
    float* b1s = w1s + 8192;        /* 128 */
    float* w2s = b1s + 128;         /* 128 */
    int y=blockIdx.x, b=blockIdx.y, tid=threadIdx.x;
    for(int i=tid;i<8192;i+=128){ int c=i>>7,x=i&127; hs[i]=g_hA[(((size_t)b*NC+c)*NH+y)*NH+x]; }
    for(int i=tid;i<8192;i+=128) w1s[i]=f1w[i];
    if(tid<128){ b1s[tid]=f1b[tid]; w2s[tid]=f2w[tid]; }
    __syncthreads();
    int x=tid;
    float v[NC];
    #pragma unroll
    for(int i=0;i<NC;i++) v[i]=hs[i*128+x];
    const float4* w14 = (const float4*)w1s;
    float acc=f2b[0];
    for(int j=0;j<128;j+=4){
        float s0=b1s[j], s1=b1s[j+1], s2=b1s[j+2], s3=b1s[j+3];
        #pragma unroll
        for(int i=0;i<NC;i++){
            float4 w = w14[(i*128+j)>>2];
            float vi = v[i];
            s0+=vi*w.x; s1+=vi*w.y; s2+=vi*w.z; s3+=vi*w.w;
        }
        acc += gelu_exact(s0)*w2s[j]   + gelu_exact(s1)*w2s[j+1]
             + gelu_exact(s2)*w2s[j+2] + gelu_exact(s3)*w2s[j+3];
    }
    out[((size_t)(b*128+y))*128+x]=acc;
}

/* ------------------------------- host ------------------------------------ */
extern "C" void kernel_launch(void* const* d_in, const int* in_sizes, int n_in,
                              void* d_out, int out_size){
    const float* x    =(const float*)d_in[0];
    const float* grd  =(const float*)d_in[1];
    const float* fc0w =(const float*)d_in[2];
    const float* fc0b =(const float*)d_in[3];
    const float* W1   =(const float*)d_in[4];
    const float* W2   =(const float*)d_in[5];
    const float* A1   =(const float*)d_in[6];
    const float* B1   =(const float*)d_in[7];
    const float* A2   =(const float*)d_in[8];
    const float* B2   =(const float*)d_in[9];
    const float* gw   =(const float*)d_in[10];
    const float* gb   =(const float*)d_in[11];
    const float* cw   =(const float*)d_in[12];
    const float* cb   =(const float*)d_in[13];
    const float* f1w  =(const float*)d_in[14];
    const float* f1b  =(const float*)d_in[15];
    const float* f2w  =(const float*)d_in[16];
    const float* f2b  =(const float*)d_in[17];
    float* out=(float*)d_out;

    const int SMFFT = 17160*4 + 5070*8 + 130*8 + 100*8;             /* 111040 */
    const int SMMIX = NC*144*8 + NC*8*8;                            /* 77824  */
    const int SMF   = (NC*132 + NC*NC + NC)*4 + (NC*NM + NH)*8;     /* 57616  */
    const int SMO   = (8192+8192+128+128)*4;                        /* 66560  */

    cudaFuncSetAttribute(kfft,   cudaFuncAttributeMaxDynamicSharedMemorySize, SMFFT);
    cudaFuncSetAttribute(kmix,   cudaFuncAttributeMaxDynamicSharedMemorySize, SMMIX);
    cudaFuncSetAttribute(kfinal, cudaFuncAttributeMaxDynamicSharedMemorySize, SMF);
    cudaFuncSetAttribute(kout,   cudaFuncAttributeMaxDynamicSharedMemorySize, SMO);

    ktw<<<1,160>>>();
    k0<<<dim3(NH,NB_),256>>>(x,grd,fc0w,fc0b);

    for(int l=0;l<4;l++){
        int curA = (l%2==0) ? 1 : 0;
        km<<<dim3(NE,2),256>>>(A1+(size_t)l*NE*NC*NR*2, B1+(size_t)l*NE*NR*NC*2,
                               A2+(size_t)l*NE*NC*NR*2, B2+(size_t)l*NE*NR*NC*2);
        kfft<<<BC,1024,SMFFT>>>(curA);
        kgate<<<NB_,32>>>(gw + (size_t)l*NC*NE, gb + (size_t)l*NE);
        kd<<<dim3(NB_,2),256>>>();
        kmix<<<dim3(8,2,NB_),256,SMMIX>>>(W1+(size_t)l*NC*NC*NM*NM*2,
                                          W2+(size_t)l*NC*NC*NM*NM*2);
        kinv1<<<BC,512>>>();
        kfinal<<<dim3(NH,NB_),256,SMF>>>(curA, cw+(size_t)l*NC*NC,
                                         cb+(size_t)l*NC, (l<3)?1:0);
    }
    kout<<<dim3(128,NB_),128,SMO>>>(f1w,f1b,f2w,f2b,out);
}

// round 14
// speedup vs baseline: 1.1731x; 1.0741x over previous
#include <cuda_runtime.h>
#include <math.h>

#define NB_ 16
#define NC 64
#define NH 130
#define NKX 66
#define NM 12
#define NE 15
#define NR 4
#define HW (NH*NH)          /* 16900 */
#define BC (NB_*NC)         /* 1024 */

/* ---------------- scratch (device globals, no runtime allocation) -------- */
__device__ float  g_hA[BC*HW];
__device__ float  g_hB[BC*HW];
__device__ float2 g_Modes[BC*24*NM];
__device__ float2 g_OutModes[BC*24*NM];
__device__ float2 g_Ty[BC*NH*NM];
__device__ float  g_sab[BC];
__device__ float  g_gate[NB_*NE];
__device__ float2 g_M1[NE*NC*NC];
__device__ float2 g_M2[NE*NC*NC];
__device__ float2 g_d1[NB_*NC*NC];
__device__ float2 g_d2[NB_*NC*NC];
__device__ float2 g_tw[NH];

__device__ __forceinline__ float gelu_exact(float v){
    return 0.5f*v*(1.f+erff(v*0.70710678118654752f));
}

/* twiddle table: tw[k] = (cos, sin)(2*pi*k/130) */
__global__ void ktw(){
    int k = threadIdx.x;
    if(k < NH){
        double th = 6.283185307179586476925286766559 * (double)k / 130.0;
        g_tw[k] = make_float2((float)cos(th), (float)sin(th));
    }
}

/* lift: h0[b,c,y,x] = concat(x,grid)@fc0_w + fc0_b ; zero pad region */
__global__ void k0(const float* __restrict__ xin, const float* __restrict__ grd,
                   const float* __restrict__ w, const float* __restrict__ bias){
    int y = blockIdx.x, b = blockIdx.y, tid = threadIdx.x;
    __shared__ float in[128*12];
    __shared__ float ws[12*NC];
    __shared__ float bs[NC];
    for(int i=tid;i<12*NC;i+=256) ws[i]=w[i];
    if(tid<NC) bs[tid]=bias[tid];
    if(y<128){
        for(int i=tid;i<128*10;i+=256){ int xx=i/10,t=i%10; in[xx*12+t]=xin[(((size_t)b*128+y)*128+xx)*10+t]; }
        for(int i=tid;i<128*2 ;i+=256){ int xx=i/2 ,t=i%2 ; in[xx*12+10+t]=grd[(((size_t)b*128+y)*128+xx)*2+t]; }
    }
    __syncthreads();
    for(int idx=tid; idx<NC*NH; idx+=256){
        int c=idx/NH, xx=idx%NH;
        float v=0.f;
        if(y<128 && xx<128){
            v=bs[c];
            #pragma unroll
            for(int t=0;t<12;t++) v += in[xx*12+t]*ws[t*NC+c];
        }
        g_hA[(((size_t)b*NC+c)*NH+y)*NH+xx]=v;
    }
}

/* ===================== fused mixed-radix 2D forward FFT ====================
 * 130 = 13*10.  Low-smem version + register twiddle recurrence in B/D. */
__global__ void __launch_bounds__(1024,2) kfft(int curA){
    extern __shared__ unsigned char s_raw[];
    float*  hs  = (float*)s_raw;            /* 130*132 floats; reused as Z/GC */
    float2* GA  = (float2*)(hs + 17160);    /* 65*78 = 5070 float2           */
    float2* tws = GA + 5070;                /* 130 */
    float2* w10 = tws + 130;                /* 100 */
    __shared__ float swred[32];
    int bc = blockIdx.x, tid = threadIdx.x;
    const float* hin = curA ? g_hA : g_hB;
    const float* hp = hin + (size_t)bc*HW;
    for(int i=tid;i<HW;i+=1024){ int y=i/130, x=i-y*130; hs[y*132+x]=hp[i]; }
    for(int i=tid;i<130;i+=1024) tws[i]=g_tw[i];
    for(int i=tid;i<100;i+=1024){ int r=i/10,p=i-r*10; w10[i]=g_tw[13*((r*p)%10)]; }
    __syncthreads();

    float2* zb = (float2*)hs;   /* Z[y][kx] : row y overlays h row y exactly */

    /* stages A+B in two y-halves (GA holds 65 rows) */
    for(int half=0; half<2; half++){
        int ybase = half*65;
        /* stage A: real radix-10 along x; store r=0..5 (Hermitian) */
        for(int it=tid; it<845; it+=1024){
            int yl = it/13, q = it-yl*13;
            int y = ybase + yl;
            float hv[10];
            #pragma unroll
            for(int p=0;p<10;p++) hv[p]=hs[y*132 + 13*p + q];
            float2* ga = GA + yl*78 + q*6;
            #pragma unroll
            for(int r=0;r<6;r++){
                float ar=0.f, ai=0.f;
                #pragma unroll
                for(int p=0;p<10;p++){
                    float2 w = w10[r*10+p];
                    ar += hv[p]*w.x;
                    ai -= hv[p]*w.y;
                }
                ga[r]=make_float2(ar,ai);
            }
        }
        __syncthreads();
        /* stage B: finish x transform; register twiddle recurrence */
        for(int it=tid; it<4290; it+=1024){
            int yl = it/66, kx = it-yl*66;
            int y = ybase + yl;
            int r = kx - (kx/10)*10;
            float sgn = 1.f;
            if(r>5){ r = 10-r; sgn = -1.f; }
            const float2* ga = GA + yl*78 + r;
            float2 wk = tws[kx];
            float wr=1.f, wi=0.f;
            float ar=0.f, ai=0.f;
            #pragma unroll
            for(int q=0;q<13;q++){
                float2 g = ga[q*6];
                float gy = g.y*sgn;
                ar += g.x*wr + gy*wi;
                ai += gy*wr - g.x*wi;
                float nr = wr*wk.x - wi*wk.y;
                wi = wr*wk.y + wi*wk.x;
                wr = nr;
            }
            zb[y*66+kx]=make_float2(ar,ai);
        }
        __syncthreads();
    }

    /* stage C: radix-10 along y, IN-PLACE in zb. */
    for(int it=tid; it<858; it+=1024){
        int q2 = it/66, kx = it-q2*66;
        float2 zp[10];
        #pragma unroll
        for(int p=0;p<10;p++) zp[p]=zb[(13*p+q2)*66 + kx];
        #pragma unroll
        for(int r=0;r<10;r++){
            float ar=0.f, ai=0.f;
            #pragma unroll
            for(int p=0;p<10;p++){
                float2 w = w10[r*10+p];
                ar += zp[p].x*w.x + zp[p].y*w.y;
                ai += zp[p].y*w.x - zp[p].x*w.y;
            }
            zb[(13*r+q2)*66 + kx]=make_float2(ar,ai);
        }
    }
    __syncthreads();

    /* stage D: finish y transform; kx-pair float4; register twiddle recurrence */
    float lsum=0.f;
    for(int it=tid; it<4290; it+=1024){
        int ky = it/33, kxp = it-ky*33, kx0 = kxp*2;
        int r2 = ky - (ky/10)*10;
        float2 wk = tws[ky];
        float wr=1.f, wi=0.f;
        float a0r=0.f,a0i=0.f,a1r=0.f,a1i=0.f;
        #pragma unroll
        for(int q=0;q<13;q++){
            float4 g = *(const float4*)(zb + (13*r2+q)*66 + kx0);
            a0r += g.x*wr + g.y*wi; a0i += g.y*wr - g.x*wi;
            a1r += g.z*wr + g.w*wi; a1i += g.w*wr - g.z*wi;
            float nr = wr*wk.x - wi*wk.y;
            wi = wr*wk.y + wi*wk.x;
            wr = nr;
        }
        lsum += sqrtf(a0r*a0r+a0i*a0i) + sqrtf(a1r*a1r+a1i*a1i);
        if(kx0<NM && (ky<NM || ky>=NH-NM)){
            int jr = (ky<NM)? ky : ky-106;
            g_Modes[((size_t)bc*24+jr)*NM+kx0  ]=make_float2(a0r,a0i);
            g_Modes[((size_t)bc*24+jr)*NM+kx0+1]=make_float2(a1r,a1i);
        }
    }
    for(int o=16;o>0;o>>=1) lsum += __shfl_down_sync(0xffffffffu, lsum, o);
    if((tid&31)==0) swred[tid>>5]=lsum;
    __syncthreads();
    if(tid<32){
        float s = swred[tid];
        for(int o=16;o>0;o>>=1) s += __shfl_down_sync(0xffffffffu, s, o);
        if(tid==0) g_sab[bc]=s/8580.f;
    }
}

/* gate: softmax(sab @ gw + gb) */
__global__ void kgate(const float* __restrict__ gw, const float* __restrict__ gb){
    int b=blockIdx.x, e=threadIdx.x;
    __shared__ float lg[NE];
    if(e<NE){
        float s=gb[e];
        for(int c=0;c<NC;c++) s += g_sab[b*NC+c]*gw[c*NE+e];
        lg[e]=s;
    }
    __syncthreads();
    if(e==0){
        float mx=-1e30f;
        for(int i=0;i<NE;i++) mx=fmaxf(mx,lg[i]);
        float den=0.f;
        for(int i=0;i<NE;i++){ lg[i]=expf(lg[i]-mx); den+=lg[i]; }
        for(int i=0;i<NE;i++) g_gate[b*NE+i]=lg[i]/den;
    }
}

/* M[e] = A[e] @ B[e]  (complex low-rank products, layer weights) */
__global__ void km(const float* __restrict__ A1,const float* __restrict__ B1,
                   const float* __restrict__ A2,const float* __restrict__ B2){
    int e=blockIdx.x, which=blockIdx.y;
    const float* A  = which? A2:A1;
    const float* Bm = which? B2:B1;
    float2* Mo = which? g_M2:g_M1;
    __shared__ float2 as[NC*NR], bs[NR*NC];
    for(int i=threadIdx.x;i<NC*NR;i+=blockDim.x){
        as[i]=make_float2(A [(e*NC*NR+i)*2], A [(e*NC*NR+i)*2+1]);
        bs[i]=make_float2(Bm[(e*NR*NC+i)*2], Bm[(e*NR*NC+i)*2+1]);
    }
    __syncthreads();
    for(int idx=threadIdx.x; idx<NC*NC; idx+=blockDim.x){
        int i=idx/NC, o=idx%NC;
        float rr=0.f, ri=0.f;
        #pragma unroll
        for(int r=0;r<NR;r++){
            float2 a=as[i*NR+r], b2=bs[r*NC+o];
            rr += a.x*b2.x - a.y*b2.y;
            ri += a.x*b2.y + a.y*b2.x;
        }
        Mo[e*NC*NC+idx]=make_float2(rr,ri);
    }
}

/* d[b] = 0.1 * sum_e g[b,e] M[e] */
__global__ void kd(){
    int b=blockIdx.x, which=blockIdx.y;
    const float2* Mm = which? g_M2 : g_M1;
    float2* dd = which? g_d2 : g_d1;
    __shared__ float gs[NE];
    if(threadIdx.x<NE) gs[threadIdx.x]=g_gate[b*NE+threadIdx.x];
    __syncthreads();
    for(int idx=threadIdx.x; idx<NC*NC; idx+=blockDim.x){
        float rr=0.f, ri=0.f;
        #pragma unroll
        for(int e=0;e<NE;e++){
            float2 m=Mm[e*NC*NC+idx];
            rr += gs[e]*m.x; ri += gs[e]*m.y;
        }
        dd[b*NC*NC+idx]=make_float2(0.1f*rr,0.1f*ri);
    }
}

/* mode mixing: o[b,o,p,q] = sum_i ft[b,i,p,q] * (W[i,o,p,q] + d[b,i,o])
 * pq-split x3 for occupancy/latency hiding: grid (8 ot, 2 half x 3 slice, b),
 * blockDim 192 -> 384 outputs/block = exactly 2 per thread. */
__global__ void __launch_bounds__(192) kmix(const float* __restrict__ W1,const float* __restrict__ W2){
    extern __shared__ unsigned char s_raw[];
    float2* tops = (float2*)s_raw;       /* 64*48 */
    float2* ds   = tops + NC*48;         /* 64*8  */
    int ot=blockIdx.x;
    int half=blockIdx.y/3, ps=blockIdx.y%3;
    int b=blockIdx.z;
    int pq0 = ps*48;
    const float2* W    = (const float2*)(half? W2:W1);
    const float2* dmat = half? g_d2 : g_d1;
    int jbase = half*NM;
    for(int i=threadIdx.x;i<NC*48;i+=192){
        int c=i/48, pq=pq0 + i%48;
        tops[i]=g_Modes[(((size_t)b*NC+c)*24 + jbase + pq/NM)*NM + pq%NM];
    }
    for(int i=threadIdx.x;i<NC*8;i+=192){
        int c=i/8, oo=i%8;
        ds[i]=dmat[((size_t)b*NC+c)*NC + ot*8+oo];
    }
    __syncthreads();
    for(int idx=threadIdx.x; idx<8*48; idx+=192){
        int oo=idx/48, pql=idx%48; int o=ot*8+oo; int pq=pq0+pql;
        float rr=0.f, ri=0.f;
        #pragma unroll 8
        for(int i=0;i<NC;i++){
            float2 t=tops[i*48+pql];
            float2 d=ds[i*8+oo];
            float2 w=W[((size_t)i*NC+o)*144+pq];
            float wr=w.x+d.x, wi=w.y+d.y;
            rr += t.x*wr - t.y*wi;
            ri += t.x*wi + t.y*wr;
        }
        g_OutModes[(((size_t)b*NC+o)*24 + jbase + pq/NM)*NM + pq%NM]=make_float2(rr,ri);
    }
}

/* inverse fft along y (only 24 nonzero bins): Ty[y,q] */
__global__ void kinv1(){
    __shared__ float2 om[24*NM];
    __shared__ float2 tws[NH];
    int bc=blockIdx.x, tid=threadIdx.x;
    for(int i=tid;i<24*NM;i+=blockDim.x) om[i]=g_OutModes[(size_t)bc*24*NM+i];
    for(int i=tid;i<NH;i+=blockDim.x) tws[i]=g_tw[i];
    __syncthreads();
    for(int idx=tid; idx<NH*NM; idx+=blockDim.x){
        int y=idx/NM, q=idx%NM;
        float rr=0.f, ri=0.f;
        #pragma unroll
        for(int j=0;j<24;j++){
            int ky = (j<NM)? j : j+106;
            int t = (ky*y)%NH;
            float2 w=tws[t];
            float2 o=om[j*NM+q];
            rr += o.x*w.x - o.y*w.y;
            ri += o.x*w.y + o.y*w.x;
        }
        g_Ty[(size_t)bc*NH*NM+idx]=make_float2(rr*(1.f/130.f), ri*(1.f/130.f));
    }
}

/* fused: irfft along x + pointwise conv + bias + (gelu) -> new h
 * o-tiled: each unit = 4 o x 4 x outputs, h4 loads shared across the 4 o's. */
__global__ void __launch_bounds__(256) kfinal(int curA, const float* __restrict__ cw,
                       const float* __restrict__ cb, int dogelu){
    extern __shared__ unsigned char s_raw[];
    float*  hs   = (float*)s_raw;           /* 64*132 floats, x padded */
    float*  cws  = hs + NC*132;             /* 4096 */
    float*  cbs  = cws + NC*NC;             /* 64 */
    float2* tys  = (float2*)(cbs + NC);     /* 64*12 */
    float2* twsl = tys + NC*NM;             /* 130 */
    const float* hin  = curA ? g_hA : g_hB;
    float*       hout = curA ? g_hB : g_hA;
    int y=blockIdx.x, b=blockIdx.y, tid=threadIdx.x;
    for(int i=tid;i<NC*NH;i+=256){ int c=i/NH,x=i-c*NH; hs[c*132+x]=hin[(((size_t)b*NC+c)*NH+y)*NH+x]; }
    for(int i=tid;i<NC*2;i+=256){ int c=i>>1; hs[c*132+130+(i&1)]=0.f; }
    for(int i=tid;i<NC*NC;i+=256) cws[i]=cw[i];
    if(tid<NC) cbs[tid]=cb[tid];
    for(int i=tid;i<NC*NM;i+=256){ int c=i/NM,q=i-c*NM; tys[i]=g_Ty[((size_t)(b*NC+c)*NH+y)*NM+q]; }
    for(int i=tid;i<NH;i+=256) twsl[i]=g_tw[i];
    __syncthreads();
    const float4* h4 = (const float4*)hs;
    for(int u=tid; u<528; u+=256){       /* 16 o-quads x 33 x-groups */
        int g = u % 33, oq = u / 33;
        int o0 = oq*4, x0 = g*4;
        /* pointwise conv: 4 o x 4 x, h4 loads reused across o */
        float acc[4][4];
        #pragma unroll
        for(int o=0;o<4;o++){
            float c0=cbs[o0+o];
            acc[o][0]=c0; acc[o][1]=c0; acc[o][2]=c0; acc[o][3]=c0;
        }
        #pragma unroll 4
        for(int i4=0;i4<16;i4++){
            float4 h0=h4[(i4*4+0)*33+g];
            float4 h1=h4[(i4*4+1)*33+g];
            float4 h2=h4[(i4*4+2)*33+g];
            float4 h3=h4[(i4*4+3)*33+g];
            #pragma unroll
            for(int o=0;o<4;o++){
                float4 c = *(const float4*)(cws + (o0+o)*NC + i4*4);
                acc[o][0] += c.x*h0.x + c.y*h1.x + c.z*h2.x + c.w*h3.x;
                acc[o][1] += c.x*h0.y + c.y*h1.y + c.z*h2.y + c.w*h3.y;
                acc[o][2] += c.x*h0.z + c.y*h1.z + c.z*h2.z + c.w*h3.z;
                acc[o][3] += c.x*h0.w + c.y*h1.w + c.z*h2.w + c.w*h3.w;
            }
        }
        /* spectral irfft along x + store, per o */
        #pragma unroll
        for(int o=0;o<4;o++){
            const float2* ty = tys + (o0+o)*NM;
            float2 t0=ty[0];
            float sac[4];
            int id[4], xa[4];
            #pragma unroll
            for(int a=0;a<4;a++){ sac[a]=t0.x; id[a]=0; xa[a]=(x0+a<NH)?(x0+a):0; }
            #pragma unroll
            for(int q=1;q<NM;q++){
                float2 t=ty[q];
                #pragma unroll
                for(int a=0;a<4;a++){
                    id[a]+=xa[a]; if(id[a]>=NH) id[a]-=NH;
                    float2 w=twsl[id[a]];
                    sac[a] += 2.f*(t.x*w.x - t.y*w.y);
                }
            }
            float* op = hout + (((size_t)b*NC+o0+o)*NH+y)*NH;
            #pragma unroll
            for(int a=0;a<4;a++){
                int x=x0+a; if(x>=NH) break;
                float v = sac[a]*(1.f/130.f) + acc[o][a];
                if(dogelu) v = gelu_exact(v);
                op[x]=v;
            }
        }
    }
}

/* head: crop + fc1 + gelu + fc2.  fc1 weights read directly from gmem
 * (warp-broadcast __ldg, L1-resident) -> smem halved -> ~2x blocks/SM. */
__global__ void __launch_bounds__(128) kout(const float* __restrict__ f1w,
        const float* __restrict__ f1b, const float* __restrict__ f2w,
        const float* __restrict__ f2b, float* __restrict__ out){
    extern __shared__ unsigned char s_raw[];
    float* hs  = (float*)s_raw;     /* 64*128 */
    float* b1s = hs + 8192;         /* 128 */
    float* w2s = b1s + 128;         /* 128 */
    int y=blockIdx.x, b=blockIdx.y, tid=threadIdx.x;
    for(int i=tid;i<8192;i+=128){ int c=i>>7,x=i&127; hs[i]=g_hA[(((size_t)b*NC+c)*NH+y)*NH+x]; }
    if(tid<128){ b1s[tid]=f1b[tid]; w2s[tid]=f2w[tid]; }
    __syncthreads();
    int x=tid;
    float v[NC];
    #pragma unroll
    for(int i=0;i<NC;i++) v[i]=hs[i*128+x];
    const float4* w14 = (const float4*)f1w;
    float acc=f2b[0];
    for(int j=0;j<128;j+=4){
        float s0=b1s[j], s1=b1s[j+1], s2=b1s[j+2], s3=b1s[j+3];
        #pragma unroll
        for(int i=0;i<NC;i++){
            float4 w = __ldg(&w14[(i*128+j)>>2]);
            float vi = v[i];
            s0+=vi*w.x; s1+=vi*w.y; s2+=vi*w.z; s3+=vi*w.w;
        }
        acc += gelu_exact(s0)*w2s[j]   + gelu_exact(s1)*w2s[j+1]
             + gelu_exact(s2)*w2s[j+2] + gelu_exact(s3)*w2s[j+3];
    }
    out[((size_t)(b*128+y))*128+x]=acc;
}

/* ------------------------------- host ------------------------------------ */
extern "C" void kernel_launch(void* const* d_in, const int* in_sizes, int n_in,
                              void* d_out, int out_size){
    const float* x    =(const float*)d_in[0];
    const float* grd  =(const float*)d_in[1];
    const float* fc0w =(const float*)d_in[2];
    const float* fc0b =(const float*)d_in[3];
    const float* W1   =(const float*)d_in[4];
    const float* W2   =(const float*)d_in[5];
    const float* A1   =(const float*)d_in[6];
    const float* B1   =(const float*)d_in[7];
    const float* A2   =(const float*)d_in[8];
    const float* B2   =(const float*)d_in[9];
    const float* gw   =(const float*)d_in[10];
    const float* gb   =(const float*)d_in[11];
    const float* cw   =(const float*)d_in[12];
    const float* cb   =(const float*)d_in[13];
    const float* f1w  =(const float*)d_in[14];
    const float* f1b  =(const float*)d_in[15];
    const float* f2w  =(const float*)d_in[16];
    const float* f2b  =(const float*)d_in[17];
    float* out=(float*)d_out;

    const int SMFFT = 17160*4 + 5070*8 + 130*8 + 100*8;             /* 111040 */
    const int SMMIX = NC*48*8 + NC*8*8;                             /* 28672  */
    const int SMF   = (NC*132 + NC*NC + NC)*4 + (NC*NM + NH)*8;     /* 57616  */
    const int SMO   = (8192+128+128)*4;                             /* 33792  */

    cudaFuncSetAttribute(kfft,   cudaFuncAttributeMaxDynamicSharedMemorySize, SMFFT);
    cudaFuncSetAttribute(kmix,   cudaFuncAttributeMaxDynamicSharedMemorySize, SMMIX);
    cudaFuncSetAttribute(kfinal, cudaFuncAttributeMaxDynamicSharedMemorySize, SMF);
    cudaFuncSetAttribute(kout,   cudaFuncAttributeMaxDynamicSharedMemorySize, SMO);

    ktw<<<1,160>>>();
    k0<<<dim3(NH,NB_),256>>>(x,grd,fc0w,fc0b);

    for(int l=0;l<4;l++){
        int curA = (l%2==0) ? 1 : 0;
        km<<<dim3(NE,2),256>>>(A1+(size_t)l*NE*NC*NR*2, B1+(size_t)l*NE*NR*NC*2,
                               A2+(size_t)l*NE*NC*NR*2, B2+(size_t)l*NE*NR*NC*2);
        kfft<<<BC,1024,SMFFT>>>(curA);
        kgate<<<NB_,32>>>(gw + (size_t)l*NC*NE, gb + (size_t)l*NE);
        kd<<<dim3(NB_,2),256>>>();
        kmix<<<dim3(8,6,NB_),192,SMMIX>>>(W1+(size_t)l*NC*NC*NM*NM*2,
                                          W2+(size_t)l*NC*NC*NM*NM*2);
        kinv1<<<BC,512>>>();
        kfinal<<<dim3(NH,NB_),256,SMF>>>(curA, cw+(size_t)l*NC*NC,
                                         cb+(size_t)l*NC, (l<3)?1:0);
    }
    kout<<<dim3(128,NB_),128,SMO>>>(f1w,f1b,f2w,f2b,out);
}

// round 16
// speedup vs baseline: 1.2393x; 1.0565x over previous
#include <cuda_runtime.h>
#include <math.h>

#define NB_ 16
#define NC 64
#define NH 130
#define NKX 66
#define NM 12
#define NE 15
#define NR 4
#define HW (NH*NH)          /* 16900 */
#define BC (NB_*NC)         /* 1024 */

/* ---------------- scratch (device globals, no runtime allocation) -------- */
__device__ float  g_hA[BC*HW];
__device__ float  g_hB[BC*HW];
__device__ float2 g_Modes[BC*24*NM];
__device__ float2 g_OutModes[BC*24*NM];
__device__ float2 g_Ty[BC*NH*NM];
__device__ float  g_sab[BC];
__device__ float2 g_d1[NB_*NC*NC];
__device__ float2 g_d2[NB_*NC*NC];
__device__ float2 g_tw[NH];

__device__ __forceinline__ float gelu_exact(float v){
    return 0.5f*v*(1.f+erff(v*0.70710678118654752f));
}

/* twiddle table: tw[k] = (cos, sin)(2*pi*k/130) */
__global__ void ktw(){
    int k = threadIdx.x;
    if(k < NH){
        double th = 6.283185307179586476925286766559 * (double)k / 130.0;
        g_tw[k] = make_float2((float)cos(th), (float)sin(th));
    }
}

/* lift: h0[b,c,y,x] = concat(x,grid)@fc0_w + fc0_b ; zero pad region */
__global__ void k0(const float* __restrict__ xin, const float* __restrict__ grd,
                   const float* __restrict__ w, const float* __restrict__ bias){
    int y = blockIdx.x, b = blockIdx.y, tid = threadIdx.x;
    __shared__ float in[128*12];
    __shared__ float ws[12*NC];
    __shared__ float bs[NC];
    for(int i=tid;i<12*NC;i+=256) ws[i]=w[i];
    if(tid<NC) bs[tid]=bias[tid];
    if(y<128){
        for(int i=tid;i<128*10;i+=256){ int xx=i/10,t=i%10; in[xx*12+t]=xin[(((size_t)b*128+y)*128+xx)*10+t]; }
        for(int i=tid;i<128*2 ;i+=256){ int xx=i/2 ,t=i%2 ; in[xx*12+10+t]=grd[(((size_t)b*128+y)*128+xx)*2+t]; }
    }
    __syncthreads();
    for(int idx=tid; idx<NC*NH; idx+=256){
        int c=idx/NH, xx=idx%NH;
        float v=0.f;
        if(y<128 && xx<128){
            v=bs[c];
            #pragma unroll
            for(int t=0;t<12;t++) v += in[xx*12+t]*ws[t*NC+c];
        }
        g_hA[(((size_t)b*NC+c)*NH+y)*NH+xx]=v;
    }
}

/* ===================== fused mixed-radix 2D forward FFT ====================
 * 130 = 13*10.  Low-smem version + register twiddle recurrence in B/D. */
__global__ void __launch_bounds__(1024,2) kfft(int curA){
    extern __shared__ unsigned char s_raw[];
    float*  hs  = (float*)s_raw;            /* 130*132 floats; reused as Z/GC */
    float2* GA  = (float2*)(hs + 17160);    /* 65*78 = 5070 float2           */
    float2* tws = GA + 5070;                /* 130 */
    float2* w10 = tws + 130;                /* 100 */
    __shared__ float swred[32];
    int bc = blockIdx.x, tid = threadIdx.x;
    const float* hin = curA ? g_hA : g_hB;
    const float* hp = hin + (size_t)bc*HW;
    for(int i=tid;i<HW;i+=1024){ int y=i/130, x=i-y*130; hs[y*132+x]=hp[i]; }
    for(int i=tid;i<130;i+=1024) tws[i]=g_tw[i];
    for(int i=tid;i<100;i+=1024){ int r=i/10,p=i-r*10; w10[i]=g_tw[13*((r*p)%10)]; }
    __syncthreads();

    float2* zb = (float2*)hs;   /* Z[y][kx] : row y overlays h row y exactly */

    /* stages A+B in two y-halves (GA holds 65 rows) */
    for(int half=0; half<2; half++){
        int ybase = half*65;
        /* stage A: real radix-10 along x; store r=0..5 (Hermitian) */
        for(int it=tid; it<845; it+=1024){
            int yl = it/13, q = it-yl*13;
            int y = ybase + yl;
            float hv[10];
            #pragma unroll
            for(int p=0;p<10;p++) hv[p]=hs[y*132 + 13*p + q];
            float2* ga = GA + yl*78 + q*6;
            #pragma unroll
            for(int r=0;r<6;r++){
                float ar=0.f, ai=0.f;
                #pragma unroll
                for(int p=0;p<10;p++){
                    float2 w = w10[r*10+p];
                    ar += hv[p]*w.x;
                    ai -= hv[p]*w.y;
                }
                ga[r]=make_float2(ar,ai);
            }
        }
        __syncthreads();
        /* stage B: finish x transform; register twiddle recurrence */
        for(int it=tid; it<4290; it+=1024){
            int yl = it/66, kx = it-yl*66;
            int y = ybase + yl;
            int r = kx - (kx/10)*10;
            float sgn = 1.f;
            if(r>5){ r = 10-r; sgn = -1.f; }
            const float2* ga = GA + yl*78 + r;
            float2 wk = tws[kx];
            float wr=1.f, wi=0.f;
            float ar=0.f, ai=0.f;
            #pragma unroll
            for(int q=0;q<13;q++){
                float2 g = ga[q*6];
                float gy = g.y*sgn;
                ar += g.x*wr + gy*wi;
                ai += gy*wr - g.x*wi;
                float nr = wr*wk.x - wi*wk.y;
                wi = wr*wk.y + wi*wk.x;
                wr = nr;
            }
            zb[y*66+kx]=make_float2(ar,ai);
        }
        __syncthreads();
    }

    /* stage C: radix-10 along y, IN-PLACE in zb. */
    for(int it=tid; it<858; it+=1024){
        int q2 = it/66, kx = it-q2*66;
        float2 zp[10];
        #pragma unroll
        for(int p=0;p<10;p++) zp[p]=zb[(13*p+q2)*66 + kx];
        #pragma unroll
        for(int r=0;r<10;r++){
            float ar=0.f, ai=0.f;
            #pragma unroll
            for(int p=0;p<10;p++){
                float2 w = w10[r*10+p];
                ar += zp[p].x*w.x + zp[p].y*w.y;
                ai += zp[p].y*w.x - zp[p].x*w.y;
            }
            zb[(13*r+q2)*66 + kx]=make_float2(ar,ai);
        }
    }
    __syncthreads();

    /* stage D: finish y transform; kx-pair float4; register twiddle recurrence */
    float lsum=0.f;
    for(int it=tid; it<4290; it+=1024){
        int ky = it/33, kxp = it-ky*33, kx0 = kxp*2;
        int r2 = ky - (ky/10)*10;
        float2 wk = tws[ky];
        float wr=1.f, wi=0.f;
        float a0r=0.f,a0i=0.f,a1r=0.f,a1i=0.f;
        #pragma unroll
        for(int q=0;q<13;q++){
            float4 g = *(const float4*)(zb + (13*r2+q)*66 + kx0);
            a0r += g.x*wr + g.y*wi; a0i += g.y*wr - g.x*wi;
            a1r += g.z*wr + g.w*wi; a1i += g.w*wr - g.z*wi;
            float nr = wr*wk.x - wi*wk.y;
            wi = wr*wk.y + wi*wk.x;
            wr = nr;
        }
        lsum += sqrtf(a0r*a0r+a0i*a0i) + sqrtf(a1r*a1r+a1i*a1i);
        if(kx0<NM && (ky<NM || ky>=NH-NM)){
            int jr = (ky<NM)? ky : ky-106;
            g_Modes[((size_t)bc*24+jr)*NM+kx0  ]=make_float2(a0r,a0i);
            g_Modes[((size_t)bc*24+jr)*NM+kx0+1]=make_float2(a1r,a1i);
        }
    }
    for(int o=16;o>0;o>>=1) lsum += __shfl_down_sync(0xffffffffu, lsum, o);
    if((tid&31)==0) swred[tid>>5]=lsum;
    __syncthreads();
    if(tid<32){
        float s = swred[tid];
        for(int o=16;o>0;o>>=1) s += __shfl_down_sync(0xffffffffu, s, o);
        if(tid==0) g_sab[bc]=s/8580.f;
    }
}

/* fused MoE: gate softmax + d[b] = 0.1 * sum_e g[b,e] (A[e] @ B[e])
 * one block per (b, which); A/B staged in smem; replaces km+kgate+kd. */
__global__ void __launch_bounds__(256) kmoe(
        const float* __restrict__ A1, const float* __restrict__ B1,
        const float* __restrict__ A2, const float* __restrict__ B2,
        const float* __restrict__ gw, const float* __restrict__ gb){
    extern __shared__ unsigned char s_raw[];
    float2* As = (float2*)s_raw;          /* [e][i][r] : 15*64*4 = 3840 */
    float2* Bs = As + 3840;               /* [e][r][o] : 15*4*64 = 3840 */
    float*  lg = (float*)(Bs + 3840);     /* 16 */
    float*  gs = lg + 16;                 /* 16 */
    int b = blockIdx.x, which = blockIdx.y, tid = threadIdx.x;
    const float2* A  = (const float2*)(which? A2:A1);
    const float2* Bm = (const float2*)(which? B2:B1);
    float2* dd = which? g_d2 : g_d1;
    for(int i=tid;i<3840;i+=256){ As[i]=A[i]; Bs[i]=Bm[i]; }
    if(tid<NE){
        float s=gb[tid];
        for(int c=0;c<NC;c++) s += g_sab[b*NC+c]*gw[c*NE+tid];
        lg[tid]=s;
    }
    __syncthreads();
    if(tid==0){
        float mx=-1e30f;
        for(int i=0;i<NE;i++) mx=fmaxf(mx,lg[i]);
        float den=0.f;
        for(int i=0;i<NE;i++){ lg[i]=expf(lg[i]-mx); den+=lg[i]; }
        for(int i=0;i<NE;i++) gs[i]=lg[i]/den;
    }
    __syncthreads();
    for(int idx=tid; idx<NC*NC; idx+=256){
        int i=idx>>6, o=idx&63;
        float rr=0.f, ri=0.f;
        #pragma unroll 3
        for(int e=0;e<NE;e++){
            float ge = gs[e];
            float er=0.f, ei=0.f;
            #pragma unroll
            for(int r=0;r<NR;r++){
                float2 a=As[(e*NC+i)*NR+r];
                float2 b2=Bs[(e*NR+r)*NC+o];
                er += a.x*b2.x - a.y*b2.y;
                ei += a.x*b2.y + a.y*b2.x;
            }
            rr += ge*er; ri += ge*ei;
        }
        dd[b*NC*NC+idx]=make_float2(0.1f*rr,0.1f*ri);
    }
}

/* mode mixing: o[b,o,p,q] = sum_i ft[b,i,p,q] * (W[i,o,p,q] + d[b,i,o])
 * pq-split x3 for occupancy/latency hiding. */
__global__ void __launch_bounds__(192) kmix(const float* __restrict__ W1,const float* __restrict__ W2){
    extern __shared__ unsigned char s_raw[];
    float2* tops = (float2*)s_raw;       /* 64*48 */
    float2* ds   = tops + NC*48;         /* 64*8  */
    int ot=blockIdx.x;
    int half=blockIdx.y/3, ps=blockIdx.y%3;
    int b=blockIdx.z;
    int pq0 = ps*48;
    const float2* W    = (const float2*)(half? W2:W1);
    const float2* dmat = half? g_d2 : g_d1;
    int jbase = half*NM;
    for(int i=threadIdx.x;i<NC*48;i+=192){
        int c=i/48, pq=pq0 + i%48;
        tops[i]=g_Modes[(((size_t)b*NC+c)*24 + jbase + pq/NM)*NM + pq%NM];
    }
    for(int i=threadIdx.x;i<NC*8;i+=192){
        int c=i/8, oo=i%8;
        ds[i]=dmat[((size_t)b*NC+c)*NC + ot*8+oo];
    }
    __syncthreads();
    for(int idx=threadIdx.x; idx<8*48; idx+=192){
        int oo=idx/48, pql=idx%48; int o=ot*8+oo; int pq=pq0+pql;
        float rr=0.f, ri=0.f;
        #pragma unroll 8
        for(int i=0;i<NC;i++){
            float2 t=tops[i*48+pql];
            float2 d=ds[i*8+oo];
            float2 w=W[((size_t)i*NC+o)*144+pq];
            float wr=w.x+d.x, wi=w.y+d.y;
            rr += t.x*wr - t.y*wi;
            ri += t.x*wi + t.y*wr;
        }
        g_OutModes[(((size_t)b*NC+o)*24 + jbase + pq/NM)*NM + pq%NM]=make_float2(rr,ri);
    }
}

/* inverse fft along y (only 24 nonzero bins): Ty[y,q] */
__global__ void kinv1(){
    __shared__ float2 om[24*NM];
    __shared__ float2 tws[NH];
    int bc=blockIdx.x, tid=threadIdx.x;
    for(int i=tid;i<24*NM;i+=blockDim.x) om[i]=g_OutModes[(size_t)bc*24*NM+i];
    for(int i=tid;i<NH;i+=blockDim.x) tws[i]=g_tw[i];
    __syncthreads();
    for(int idx=tid; idx<NH*NM; idx+=blockDim.x){
        int y=idx/NM, q=idx%NM;
        float rr=0.f, ri=0.f;
        #pragma unroll
        for(int j=0;j<24;j++){
            int ky = (j<NM)? j : j+106;
            int t = (ky*y)%NH;
            float2 w=tws[t];
            float2 o=om[j*NM+q];
            rr += o.x*w.x - o.y*w.y;
            ri += o.x*w.y + o.y*w.x;
        }
        g_Ty[(size_t)bc*NH*NM+idx]=make_float2(rr*(1.f/130.f), ri*(1.f/130.f));
    }
}

/* fused: irfft along x + pointwise conv + bias + (gelu) -> new h
 * o-tiled conv (verified) + spectral via register twiddle recurrence
 * (replaces bank-conflicted twsl gathers: tw[(q x)%130] = tw[x]^q). */
__global__ void __launch_bounds__(256) kfinal(int curA, const float* __restrict__ cw,
                       const float* __restrict__ cb, int dogelu){
    extern __shared__ unsigned char s_raw[];
    float*  hs   = (float*)s_raw;           /* 64*132 floats, x padded */
    float*  cws  = hs + NC*132;             /* 4096 */
    float*  cbs  = cws + NC*NC;             /* 64 */
    float2* tys  = (float2*)(cbs + NC);     /* 64*12 */
    float2* twsl = tys + NC*NM;             /* 130 */
    const float* hin  = curA ? g_hA : g_hB;
    float*       hout = curA ? g_hB : g_hA;
    int y=blockIdx.x, b=blockIdx.y, tid=threadIdx.x;
    for(int i=tid;i<NC*NH;i+=256){ int c=i/NH,x=i-c*NH; hs[c*132+x]=hin[(((size_t)b*NC+c)*NH+y)*NH+x]; }
    for(int i=tid;i<NC*2;i+=256){ int c=i>>1; hs[c*132+130+(i&1)]=0.f; }
    for(int i=tid;i<NC*NC;i+=256) cws[i]=cw[i];
    if(tid<NC) cbs[tid]=cb[tid];
    for(int i=tid;i<NC*NM;i+=256){ int c=i/NM,q=i-c*NM; tys[i]=g_Ty[((size_t)(b*NC+c)*NH+y)*NM+q]; }
    for(int i=tid;i<NH;i+=256) twsl[i]=g_tw[i];
    __syncthreads();
    const float4* h4 = (const float4*)hs;
    for(int u=tid; u<528; u+=256){       /* 16 o-quads x 33 x-groups */
        int g = u % 33, oq = u / 33;
        int o0 = oq*4, x0 = g*4;
        /* pointwise conv: 4 o x 4 x, h4 loads reused across o */
        float acc[4][4];
        #pragma unroll
        for(int o=0;o<4;o++){
            float c0=cbs[o0+o];
            acc[o][0]=c0; acc[o][1]=c0; acc[o][2]=c0; acc[o][3]=c0;
        }
        #pragma unroll 4
        for(int i4=0;i4<16;i4++){
            float4 h0=h4[(i4*4+0)*33+g];
            float4 h1=h4[(i4*4+1)*33+g];
            float4 h2=h4[(i4*4+2)*33+g];
            float4 h3=h4[(i4*4+3)*33+g];
            #pragma unroll
            for(int o=0;o<4;o++){
                float4 c = *(const float4*)(cws + (o0+o)*NC + i4*4);
                acc[o][0] += c.x*h0.x + c.y*h1.x + c.z*h2.x + c.w*h3.x;
                acc[o][1] += c.x*h0.y + c.y*h1.y + c.z*h2.y + c.w*h3.y;
                acc[o][2] += c.x*h0.z + c.y*h1.z + c.z*h2.z + c.w*h3.z;
                acc[o][3] += c.x*h0.w + c.y*h1.w + c.z*h2.w + c.w*h3.w;
            }
        }
        /* spectral irfft along x: per-a rotation by tw[x] per q step */
        float2 bw[4];
        #pragma unroll
        for(int a=0;a<4;a++){ int xx=x0+a; bw[a]=twsl[(xx<NH)?xx:0]; }
        #pragma unroll
        for(int o=0;o<4;o++){
            const float2* ty = tys + (o0+o)*NM;
            float2 t0=ty[0];
            float sac[4], wr[4], wi[4];
            #pragma unroll
            for(int a=0;a<4;a++){ sac[a]=t0.x; wr[a]=1.f; wi[a]=0.f; }
            #pragma unroll
            for(int q=1;q<NM;q++){
                float2 t=ty[q];
                #pragma unroll
                for(int a=0;a<4;a++){
                    float nr = wr[a]*bw[a].x - wi[a]*bw[a].y;
                    wi[a] = wr[a]*bw[a].y + wi[a]*bw[a].x;
                    wr[a] = nr;
                    sac[a] += 2.f*(t.x*wr[a] - t.y*wi[a]);
                }
            }
            float* op = hout + (((size_t)b*NC+o0+o)*NH+y)*NH;
            #pragma unroll
            for(int a=0;a<4;a++){
                int x=x0+a; if(x>=NH) break;
                float v = sac[a]*(1.f/130.f) + acc[o][a];
                if(dogelu) v = gelu_exact(v);
                op[x]=v;
            }
        }
    }
}

/* head: crop + fc1 + gelu + fc2.  fc1 weights read directly from gmem. */
__global__ void __launch_bounds__(128) kout(const float* __restrict__ f1w,
        const float* __restrict__ f1b, const float* __restrict__ f2w,
        const float* __restrict__ f2b, float* __restrict__ out){
    extern __shared__ unsigned char s_raw[];
    float* hs  = (float*)s_raw;     /* 64*128 */
    float* b1s = hs + 8192;         /* 128 */
    float* w2s = b1s + 128;         /* 128 */
    int y=blockIdx.x, b=blockIdx.y, tid=threadIdx.x;
    for(int i=tid;i<8192;i+=128){ int c=i>>7,x=i&127; hs[i]=g_hA[(((size_t)b*NC+c)*NH+y)*NH+x]; }
    if(tid<128){ b1s[tid]=f1b[tid]; w2s[tid]=f2w[tid]; }
    __syncthreads();
    int x=tid;
    float v[NC];
    #pragma unroll
    for(int i=0;i<NC;i++) v[i]=hs[i*128+x];
    const float4* w14 = (const float4*)f1w;
    float acc=f2b[0];
    for(int j=0;j<128;j+=4){
        float s0=b1s[j], s1=b1s[j+1], s2=b1s[j+2], s3=b1s[j+3];
        #pragma unroll
        for(int i=0;i<NC;i++){
            float4 w = __ldg(&w14[(i*128+j)>>2]);
            float vi = v[i];
            s0+=vi*w.x; s1+=vi*w.y; s2+=vi*w.z; s3+=vi*w.w;
        }
        acc += gelu_exact(s0)*w2s[j]   + gelu_exact(s1)*w2s[j+1]
             + gelu_exact(s2)*w2s[j+2] + gelu_exact(s3)*w2s[j+3];
    }
    out[((size_t)(b*128+y))*128+x]=acc;
}

/* ------------------------------- host ------------------------------------ */
extern "C" void kernel_launch(void* const* d_in, const int* in_sizes, int n_in,
                              void* d_out, int out_size){
    const float* x    =(const float*)d_in[0];
    const float* grd  =(const float*)d_in[1];
    const float* fc0w =(const float*)d_in[2];
    const float* fc0b =(const float*)d_in[3];
    const float* W1   =(const float*)d_in[4];
    const float* W2   =(const float*)d_in[5];
    const float* A1   =(const float*)d_in[6];
    const float* B1   =(const float*)d_in[7];
    const float* A2   =(const float*)d_in[8];
    const float* B2   =(const float*)d_in[9];
    const float* gw   =(const float*)d_in[10];
    const float* gb   =(const float*)d_in[11];
    const float* cw   =(const float*)d_in[12];
    const float* cb   =(const float*)d_in[13];
    const float* f1w  =(const float*)d_in[14];
    const float* f1b  =(const float*)d_in[15];
    const float* f2w  =(const float*)d_in[16];
    const float* f2b  =(const float*)d_in[17];
    float* out=(float*)d_out;

    const int SMFFT = 17160*4 + 5070*8 + 130*8 + 100*8;             /* 111040 */
    const int SMMOE = 3840*8*2 + 32*4;                              /* 61568  */
    const int SMMIX = NC*48*8 + NC*8*8;                             /* 28672  */
    const int SMF   = (NC*132 + NC*NC + NC)*4 + (NC*NM + NH)*8;     /* 57616  */
    const int SMO   = (8192+128+128)*4;                             /* 33792  */

    cudaFuncSetAttribute(kfft,   cudaFuncAttributeMaxDynamicSharedMemorySize, SMFFT);
    cudaFuncSetAttribute(kmoe,   cudaFuncAttributeMaxDynamicSharedMemorySize, SMMOE);
    cudaFuncSetAttribute(kmix,   cudaFuncAttributeMaxDynamicSharedMemorySize, SMMIX);
    cudaFuncSetAttribute(kfinal, cudaFuncAttributeMaxDynamicSharedMemorySize, SMF);
    cudaFuncSetAttribute(kout,   cudaFuncAttributeMaxDynamicSharedMemorySize, SMO);

    ktw<<<1,160>>>();
    k0<<<dim3(NH,NB_),256>>>(x,grd,fc0w,fc0b);

    for(int l=0;l<4;l++){
        int curA = (l%2==0) ? 1 : 0;
        kfft<<<BC,1024,SMFFT>>>(curA);
        kmoe<<<dim3(NB_,2),256,SMMOE>>>(
            A1+(size_t)l*NE*NC*NR*2, B1+(size_t)l*NE*NR*NC*2,
            A2+(size_t)l*NE*NC*NR*2, B2+(size_t)l*NE*NR*NC*2,
            gw + (size_t)l*NC*NE, gb + (size_t)l*NE);
        kmix<<<dim3(8,6,NB_),192,SMMIX>>>(W1+(size_t)l*NC*NC*NM*NM*2,
                                          W2+(size_t)l*NC*NC*NM*NM*2);
        kinv1<<<BC,512>>>();
        kfinal<<<dim3(NH,NB_),256,SMF>>>(curA, cw+(size_t)l*NC*NC,
                                         cb+(size_t)l*NC, (l<3)?1:0);
    }
    kout<<<dim3(128,NB_),128,SMO>>>(f1w,f1b,f2w,f2b,out);
}